// round 7
// baseline (speedup 1.0000x reference)
#include <cuda_runtime.h>

#define Ll 4096
#define Dd 128
#define Cc 32
#define NCH 128
#define BHh 16
#define DVB 16
#define NDVB 8
#define ELEMS (BHh*Ll*Dd)
#define O_ELEMS ((size_t)ELEMS)
#define NCHK (BHh*NCH)   // 2048 chunks total

// Scratch (__device__ globals; allocation-free rule)
__device__ float g_qn [ELEMS];            // q normalized, row-major (epilogue)
__device__ float g_u  [ELEMS];            // u = T(v*beta), row-major (scan)
__device__ float g_wT [NCHK*4096];        // per chunk: w^T [d][32] (scan)
__device__ float g_kT [NCHK*4096];        // per chunk: k^T [d][32] (scan)
__device__ float g_att[NCHK*1024];        // attn_local (epilogue)
__device__ float g_S  [(size_t)NCHK*16384]; // per chunk: S_i col-major [c][d]
__device__ float g_u2 [NCHK*4096];        // per chunk: u' col-major [c][r]

// ----------------------------------------------------------------------------
// Kernel 1: per-chunk preprocessing. grid = 2048, block = 128
// ----------------------------------------------------------------------------
__global__ __launch_bounds__(128) void prep_kernel(
    const float* __restrict__ q, const float* __restrict__ k,
    const float* __restrict__ v, const float* __restrict__ beta)
{
    extern __shared__ float sm1[];
    float* sqT   = sm1;                // [128][33]
    float* skT   = sqT + 4224;         // [128][33]
    float* svb   = skT + 4224;         // [32][128]
    float* sA    = svb + 4096;         // [32][33]
    float* sbeta = sA  + 1056;         // [32]

    const int tid  = threadIdx.x;
    const int lane = tid & 31;
    const int warp = tid >> 5;
    const int bh = blockIdx.x >> 7;
    const int ci = blockIdx.x & 127;
    const int chk = blockIdx.x;
    const size_t base = ((size_t)bh*Ll + (size_t)ci*Cc)*Dd;

    for (int r = warp*8; r < warp*8 + 8; ++r) {
        float bet = beta[(size_t)bh*Ll + ci*Cc + r];
        const float4 xq = *(const float4*)(q + base + r*Dd + lane*4);
        const float4 xk = *(const float4*)(k + base + r*Dd + lane*4);
        const float4 xv = *(const float4*)(v + base + r*Dd + lane*4);
        float s2q = xq.x*xq.x + xq.y*xq.y + xq.z*xq.z + xq.w*xq.w;
        float s2k = xk.x*xk.x + xk.y*xk.y + xk.z*xk.z + xk.w*xk.w;
        #pragma unroll
        for (int o = 16; o; o >>= 1) {
            s2q += __shfl_xor_sync(0xffffffffu, s2q, o);
            s2k += __shfl_xor_sync(0xffffffffu, s2k, o);
        }
        float iq = rsqrtf(s2q + 1e-6f);
        float ik = rsqrtf(s2k + 1e-6f);
        float4 nq = make_float4(xq.x*iq, xq.y*iq, xq.z*iq, xq.w*iq);
        float4 nk = make_float4(xk.x*ik, xk.y*ik, xk.z*ik, xk.w*ik);
        *(float4*)(g_qn + base + r*Dd + lane*4) = nq;
        const int d0 = lane*4;
        sqT[(d0+0)*33 + r] = nq.x; sqT[(d0+1)*33 + r] = nq.y;
        sqT[(d0+2)*33 + r] = nq.z; sqT[(d0+3)*33 + r] = nq.w;
        skT[(d0+0)*33 + r] = nk.x; skT[(d0+1)*33 + r] = nk.y;
        skT[(d0+2)*33 + r] = nk.z; skT[(d0+3)*33 + r] = nk.w;
        *(float4*)(svb + r*Dd + d0) = make_float4(xv.x*bet, xv.y*bet, xv.z*bet, xv.w*bet);
        if (lane == 0) sbeta[r] = bet;
    }
    __syncthreads();

    // write k^T [d][32] for scan
    {
        const int d = tid;
        #pragma unroll
        for (int r4 = 0; r4 < 32; r4 += 4) {
            *(float4*)&g_kT[(size_t)chk*4096 + d*32 + r4] = make_float4(
                skT[d*33+r4], skT[d*33+r4+1], skT[d*33+r4+2], skT[d*33+r4+3]);
        }
    }

    // A = -beta_i (k_i.k_j) strict-lower ; E = q_i.k_j incl-lower -> g_att
    {
        const int i0 = (tid >> 3) * 2;
        const int j0 = (tid & 7) * 4;
        float a00=0,a01=0,a02=0,a03=0,a10=0,a11=0,a12=0,a13=0;
        float e00=0,e01=0,e02=0,e03=0,e10=0,e11=0,e12=0,e13=0;
        #pragma unroll 4
        for (int d = 0; d < Dd; ++d) {
            const float* kc = skT + d*33;
            const float* qc = sqT + d*33;
            float b0=kc[j0], b1=kc[j0+1], b2=kc[j0+2], b3=kc[j0+3];
            float ka0=kc[i0], ka1=kc[i0+1], qa0=qc[i0], qa1=qc[i0+1];
            a00+=ka0*b0; a01+=ka0*b1; a02+=ka0*b2; a03+=ka0*b3;
            a10+=ka1*b0; a11+=ka1*b1; a12+=ka1*b2; a13+=ka1*b3;
            e00+=qa0*b0; e01+=qa0*b1; e02+=qa0*b2; e03+=qa0*b3;
            e10+=qa1*b0; e11+=qa1*b1; e12+=qa1*b2; e13+=qa1*b3;
        }
        float nb0 = -sbeta[i0], nb1 = -sbeta[i0+1];
        sA[(i0  )*33+j0  ] = (j0  <i0  ) ? nb0*a00 : 0.f;
        sA[(i0  )*33+j0+1] = (j0+1<i0  ) ? nb0*a01 : 0.f;
        sA[(i0  )*33+j0+2] = (j0+2<i0  ) ? nb0*a02 : 0.f;
        sA[(i0  )*33+j0+3] = (j0+3<i0  ) ? nb0*a03 : 0.f;
        sA[(i0+1)*33+j0  ] = (j0  <i0+1) ? nb1*a10 : 0.f;
        sA[(i0+1)*33+j0+1] = (j0+1<i0+1) ? nb1*a11 : 0.f;
        sA[(i0+1)*33+j0+2] = (j0+2<i0+1) ? nb1*a12 : 0.f;
        sA[(i0+1)*33+j0+3] = (j0+3<i0+1) ? nb1*a13 : 0.f;
        float* ga = g_att + (size_t)chk*1024;
        ga[(i0  )*Cc+j0  ] = (j0  <=i0  ) ? e00 : 0.f;
        ga[(i0  )*Cc+j0+1] = (j0+1<=i0  ) ? e01 : 0.f;
        ga[(i0  )*Cc+j0+2] = (j0+2<=i0  ) ? e02 : 0.f;
        ga[(i0  )*Cc+j0+3] = (j0+3<=i0  ) ? e03 : 0.f;
        ga[(i0+1)*Cc+j0  ] = (j0  <=i0+1) ? e10 : 0.f;
        ga[(i0+1)*Cc+j0+1] = (j0+1<=i0+1) ? e11 : 0.f;
        ga[(i0+1)*Cc+j0+2] = (j0+2<=i0+1) ? e12 : 0.f;
        ga[(i0+1)*Cc+j0+3] = (j0+3<=i0+1) ? e13 : 0.f;
    }
    __syncthreads();

    // forward substitution (warp 0), then += I
    if (warp == 0) {
        for (int i = 1; i < 32; ++i) {
            float rv  = sA[i*33 + lane];
            float acc = rv;
            for (int j = 0; j < i; ++j)
                acc += __shfl_sync(0xffffffffu, rv, j) * sA[j*33 + lane];
            sA[i*33 + lane] = acc;
            __syncwarp();
        }
        sA[lane*33 + lane] += 1.0f;
    }
    __syncthreads();

    // u = T(v*beta) row-major ; w = T(k*beta) -> g_wT transposed
    {
        const int d = tid;
        #pragma unroll
        for (int rb = 0; rb < 4; ++rb) {
            const int r0 = rb*8;
            float ar[8];
            #pragma unroll
            for (int rr = 0; rr < 8; ++rr) ar[rr] = sA[(r0+rr)*33 + lane];
            float au[8] = {0,0,0,0,0,0,0,0};
            float aw[8] = {0,0,0,0,0,0,0,0};
            for (int j = 0; j < 32; ++j) {
                float vb = svb[j*Dd + d];
                float kb = skT[d*33 + j] * sbeta[j];
                #pragma unroll
                for (int rr = 0; rr < 8; ++rr) {
                    float a = __shfl_sync(0xffffffffu, ar[rr], j);
                    au[rr] += a*vb;
                    aw[rr] += a*kb;
                }
            }
            #pragma unroll
            for (int rr = 0; rr < 8; ++rr)
                g_u[base + (size_t)(r0+rr)*Dd + d] = au[rr];
            *(float4*)&g_wT[(size_t)chk*4096 + d*32 + r0    ] = make_float4(aw[0],aw[1],aw[2],aw[3]);
            *(float4*)&g_wT[(size_t)chk*4096 + d*32 + r0 + 4] = make_float4(aw[4],aw[5],aw[6],aw[7]);
        }
    }
}

// ----------------------------------------------------------------------------
// Kernel 2: sequential scan (state only). grid = (8,16), block = 1024 (32 warps)
// ----------------------------------------------------------------------------
#define WST 36
#define KST 33
#define SST 20
#define SW_SZ (128*WST)   // 4608
#define SK_SZ (128*KST)   // 4224

__global__ __launch_bounds__(1024, 1) void scan_kernel(float* __restrict__ out)
{
    extern __shared__ float sm2[];
    float* swT = sm2;                   // [2][128][36]
    float* skT = swT + 2*SW_SZ;         // [2][128][33]
    float* sS  = skT + 2*SK_SZ;         // [128][20]
    float* sYp = sS  + 2560;            // [8][32][20]
    float* su2 = sYp + 5120;            // [32][20]

    const int cb = blockIdx.x;
    const int bh = blockIdx.y;
    const int colbase = cb * DVB;
    const int tid  = threadIdx.x;
    const int lane = tid & 31;
    const int warp = tid >> 5;

    // Y roles (all 32 warps): dq = K-quarter-of-8, cg = 4-col group
    const int dq = warp >> 2;           // 0..7
    const int cg = (warp & 3) * 4;      // 0,4,8,12
    // S-update roles (warps 0..15)
    const int sd  = (warp >> 2)*32 + lane;   // valid for warp<16
    const int ucg = (warp & 3) * 4;
    // u' roles (tid<128)
    const int tw4 = (tid >> 5) * 4;

    // prefetch/commit roles:
    //   tid <  512: k holder  (2 float4)  -> skT commit (8 scalar stores)
    //   tid >= 512: w holder  (2 float4)  -> swT commit (2 float4 stores)
    const int t2 = tid & 511;
    const int cd = t2 >> 2;             // 0..127
    const int cr = (t2 & 3) * 8;        // 0,8,16,24

    float4 Sreg = make_float4(0.f, 0.f, 0.f, 0.f);
    for (int i = tid; i < 2560; i += 1024) sS[i] = 0.f;

    float4 ra0, ra1, ru;

    // prefetch chunk 0
    {
        const size_t tb = ((size_t)(bh*NCH))*4096;
        const float* src = (tid < 512) ? g_kT : g_wT;
        ra0 = *(const float4*)(src + tb + t2*8);
        ra1 = *(const float4*)(src + tb + t2*8 + 4);
        if (tid < 128)
            ru = *(const float4*)(g_u + ((size_t)bh*Ll + (tid&31))*Dd + colbase + tw4);
    }
    // commit chunk 0 to buffer 0
    if (tid < 512) {
        float* dk = skT;
        dk[cd*KST+cr  ]=ra0.x; dk[cd*KST+cr+1]=ra0.y;
        dk[cd*KST+cr+2]=ra0.z; dk[cd*KST+cr+3]=ra0.w;
        dk[cd*KST+cr+4]=ra1.x; dk[cd*KST+cr+5]=ra1.y;
        dk[cd*KST+cr+6]=ra1.z; dk[cd*KST+cr+7]=ra1.w;
    } else {
        *(float4*)&swT[cd*WST + cr    ] = ra0;
        *(float4*)&swT[cd*WST + cr + 4] = ra1;
    }
    __syncthreads();

    for (int ci = 0; ci < NCH; ++ci) {
        const int buf = ci & 1;
        const int chk = bh*NCH + ci;

        // warps 16-31: persist S_i (pre-chunk state) from smem, col-major [c][d]
        if (warp >= 16) {
            const int c  = (tid - 512) >> 5;    // 0..15
            const int d4 = lane * 4;
            float4 f = make_float4(sS[(d4  )*SST + c], sS[(d4+1)*SST + c],
                                   sS[(d4+2)*SST + c], sS[(d4+3)*SST + c]);
            *(float4*)&g_S[(size_t)chk*16384 + (size_t)(colbase + c)*128 + d4] = f;
        }
        // prefetch chunk ci+1
        float4 ru_next = ru;
        if (ci + 1 < NCH) {
            const size_t tb = ((size_t)(chk+1))*4096;
            const float* src = (tid < 512) ? g_kT : g_wT;
            ra0 = *(const float4*)(src + tb + t2*8);
            ra1 = *(const float4*)(src + tb + t2*8 + 4);
            if (tid < 128)
                ru_next = *(const float4*)(g_u + ((size_t)bh*Ll + (size_t)(ci+1)*Cc + (tid&31))*Dd + colbase + tw4);
        }

        // Y: partial of w(32x128) @ S(128x16); this warp: d-range dq*16..+15, cols cg..+3
        {
            const float* xw = swT + buf*SW_SZ;
            float4 y = make_float4(0,0,0,0);
            #pragma unroll
            for (int j = 0; j < 16; ++j) {
                const int jd = dq*16 + j;
                float x = xw[jd*WST + lane];
                float4 s = *(const float4*)&sS[jd*SST + cg];
                y.x += x*s.x; y.y += x*s.y; y.z += x*s.z; y.w += x*s.w;
            }
            *(float4*)&sYp[dq*640 + lane*SST + cg] = y;
        }
        __syncthreads();

        // u' = u - w@S  (warps 0-3)
        if (tid < 128) {
            const int r = lane;
            float4 acc = ru;
            #pragma unroll
            for (int d8 = 0; d8 < 8; ++d8) {
                float4 p = *(const float4*)&sYp[d8*640 + r*SST + tw4];
                acc.x -= p.x; acc.y -= p.y; acc.z -= p.z; acc.w -= p.w;
            }
            *(float4*)&su2[r*SST + tw4] = acc;
            float* gu = g_u2 + (size_t)chk*4096 + (colbase + tw4)*32 + r;
            gu[0] = acc.x; gu[32] = acc.y; gu[64] = acc.z; gu[96] = acc.w;
        }
        // commit next chunk into other buffer (overlaps u')
        if (ci + 1 < NCH) {
            const int b2 = (ci+1) & 1;
            if (tid < 512) {
                float* dk = skT + b2*SK_SZ;
                dk[cd*KST+cr  ]=ra0.x; dk[cd*KST+cr+1]=ra0.y;
                dk[cd*KST+cr+2]=ra0.z; dk[cd*KST+cr+3]=ra0.w;
                dk[cd*KST+cr+4]=ra1.x; dk[cd*KST+cr+5]=ra1.y;
                dk[cd*KST+cr+6]=ra1.z; dk[cd*KST+cr+7]=ra1.w;
            } else {
                float* dw = swT + b2*SW_SZ;
                *(float4*)&dw[cd*WST + cr    ] = ra0;
                *(float4*)&dw[cd*WST + cr + 4] = ra1;
            }
            ru = ru_next;
        }
        __syncthreads();

        // S += k^T @ u'  (warps 0-15, register-resident S tile)
        if (warp < 16) {
            const float* kp = skT + buf*SK_SZ + sd*KST;
            #pragma unroll 8
            for (int r = 0; r < 32; ++r) {
                float kk = kp[r];
                float4 u4 = *(const float4*)&su2[r*SST + ucg];
                Sreg.x += kk*u4.x; Sreg.y += kk*u4.y;
                Sreg.z += kk*u4.z; Sreg.w += kk*u4.w;
            }
            *(float4*)&sS[sd*SST + ucg] = Sreg;
        }
        __syncthreads();
    }

    // final S -> out (row-major [bh][dk][dv])
    if (warp < 16)
        *(float4*)&out[O_ELEMS + ((size_t)bh*Dd + sd)*Dd + colbase + ucg] = Sreg;
}

// ----------------------------------------------------------------------------
// Kernel 3: epilogue o = q@S_i + A@u'_i. grid = (NCH, BHh), block = 256.
// ----------------------------------------------------------------------------
#define AST 36

__global__ __launch_bounds__(256) void epi_kernel(float* __restrict__ out)
{
    extern __shared__ float sm3[];
    float* sS = sm3;              // [128][132] row-major S
    float* sq = sS + 128*132;     // [32][132]
    float* su = sq + 32*132;      // [32][132]
    float* sA = su + 32*132;      // [32][36]

    const int ci = blockIdx.x;
    const int bh = blockIdx.y;
    const int chk = bh*NCH + ci;
    const int tid = threadIdx.x;
    const size_t qbase = ((size_t)bh*Ll + (size_t)ci*Cc)*Dd;

    // stage S (col-major gmem -> row-major smem)
    {
        const int c = tid >> 1;
        const int db = (tid & 1) * 64;
        const float* gs = g_S + (size_t)chk*16384 + (size_t)c*128 + db;
        #pragma unroll
        for (int i = 0; i < 16; ++i) {
            float4 f = *(const float4*)(gs + i*4);
            int d = db + i*4;
            sS[(d  )*132 + c] = f.x; sS[(d+1)*132 + c] = f.y;
            sS[(d+2)*132 + c] = f.z; sS[(d+3)*132 + c] = f.w;
        }
    }
    // stage q (row-major)
    {
        #pragma unroll
        for (int t = 0; t < 4; ++t) {
            int i4 = (tid + t*256) * 4;
            float4 f = *(const float4*)(g_qn + qbase + i4);
            *(float4*)&sq[(i4 >> 7)*132 + (i4 & 127)] = f;
        }
    }
    // stage u' (col-major gmem -> row-major smem)
    {
        #pragma unroll
        for (int t = 0; t < 4; ++t) {
            int i4 = (tid + t*256) * 4;        // c = i4>>5, r = i4&31
            float4 f = *(const float4*)(g_u2 + (size_t)chk*4096 + i4);
            int c = i4 >> 5, r = i4 & 31;
            su[(r  )*132 + c] = f.x; su[(r+1)*132 + c] = f.y;
            su[(r+2)*132 + c] = f.z; su[(r+3)*132 + c] = f.w;
        }
    }
    // stage A (stride 36: 16B-aligned float4 rows)
    {
        int i4 = tid * 4;
        float4 f = *(const float4*)(g_att + (size_t)chk*1024 + i4);
        *(float4*)&sA[(i4 >> 5)*AST + (i4 & 31)] = f;
    }
    __syncthreads();

    // compute: thread tile 2 rows x 8 cols
    const int m0 = (tid >> 4) * 2;
    const int m1 = m0 + 1;
    const int cbk = (tid & 15) * 8;
    float4 a00 = make_float4(0,0,0,0), a01 = a00, a10 = a00, a11 = a00;
    #pragma unroll 8
    for (int d = 0; d < 128; ++d) {
        float q0 = sq[m0*132 + d];
        float q1 = sq[m1*132 + d];
        float4 s0 = *(const float4*)&sS[d*132 + cbk];
        float4 s1 = *(const float4*)&sS[d*132 + cbk + 4];
        a00.x += q0*s0.x; a00.y += q0*s0.y; a00.z += q0*s0.z; a00.w += q0*s0.w;
        a01.x += q0*s1.x; a01.y += q0*s1.y; a01.z += q0*s1.z; a01.w += q0*s1.w;
        a10.x += q1*s0.x; a10.y += q1*s0.y; a10.z += q1*s0.z; a10.w += q1*s0.w;
        a11.x += q1*s1.x; a11.y += q1*s1.y; a11.z += q1*s1.z; a11.w += q1*s1.w;
    }
    #pragma unroll 8
    for (int j = 0; j < 32; ++j) {
        float p0 = sA[m0*AST + j];
        float p1 = sA[m1*AST + j];
        float4 u0 = *(const float4*)&su[j*132 + cbk];
        float4 u1 = *(const float4*)&su[j*132 + cbk + 4];
        a00.x += p0*u0.x; a00.y += p0*u0.y; a00.z += p0*u0.z; a00.w += p0*u0.w;
        a01.x += p0*u1.x; a01.y += p0*u1.y; a01.z += p0*u1.z; a01.w += p0*u1.w;
        a10.x += p1*u0.x; a10.y += p1*u0.y; a10.z += p1*u0.z; a10.w += p1*u0.w;
        a11.x += p1*u1.x; a11.y += p1*u1.y; a11.z += p1*u1.z; a11.w += p1*u1.w;
    }
    float* o0 = out + qbase + (size_t)m0*Dd + cbk;
    float* o1 = out + qbase + (size_t)m1*Dd + cbk;
    *(float4*)(o0)     = a00; *(float4*)(o0 + 4) = a01;
    *(float4*)(o1)     = a10; *(float4*)(o1 + 4) = a11;
}

// ----------------------------------------------------------------------------
extern "C" void kernel_launch(void* const* d_in, const int* in_sizes, int n_in,
                              void* d_out, int out_size)
{
    const float* q    = (const float*)d_in[0];
    const float* k    = (const float*)d_in[1];
    const float* v    = (const float*)d_in[2];
    const float* beta = (const float*)d_in[3];
    float* out = (float*)d_out;

    const int smem1 = (2*4224 + 4096 + 1056 + 32) * 4;                 // 54528
    const int smem2 = (2*SW_SZ + 2*SK_SZ + 2560 + 5120 + 640) * 4;     // 103936
    const int smem3 = (128*132 + 32*132 + 32*132 + 32*AST) * 4;        // 105984
    cudaFuncSetAttribute(prep_kernel, cudaFuncAttributeMaxDynamicSharedMemorySize, smem1);
    cudaFuncSetAttribute(scan_kernel, cudaFuncAttributeMaxDynamicSharedMemorySize, smem2);
    cudaFuncSetAttribute(epi_kernel,  cudaFuncAttributeMaxDynamicSharedMemorySize, smem3);

    prep_kernel<<<NCHK, 128, smem1>>>(q, k, v, beta);
    scan_kernel<<<dim3(NDVB, BHh), 1024, smem2>>>(out);
    epi_kernel<<<dim3(NCH, BHh), 256, smem3>>>(out);
}

// round 8
// speedup vs baseline: 1.1014x; 1.1014x over previous
#include <cuda_runtime.h>

#define Ll 4096
#define Dd 128
#define Cc 32
#define NCH 128
#define BHh 16
#define DVB 16
#define NDVB 8
#define ELEMS (BHh*Ll*Dd)
#define O_ELEMS ((size_t)ELEMS)
#define NCHK (BHh*NCH)

typedef unsigned long long u64t;
__device__ __forceinline__ u64t pk2s(float a){
    u64t r; asm("mov.b64 %0,{%1,%1};" : "=l"(r) : "f"(a)); return r;
}
__device__ __forceinline__ u64t f2(u64t a, u64t b, u64t c){
    u64t d; asm("fma.rn.f32x2 %0,%1,%2,%3;" : "=l"(d) : "l"(a), "l"(b), "l"(c)); return d;
}
__device__ __forceinline__ float2 up2(u64t p){
    float lo, hi; asm("mov.b64 {%0,%1},%2;" : "=f"(lo), "=f"(hi) : "l"(p));
    return make_float2(lo, hi);
}

// Scratch
__device__ float g_qn [ELEMS];            // q normalized, row-major (epilogue)
__device__ float g_u  [ELEMS];            // u = T(v*beta), row-major (scan)
__device__ float g_w  [ELEMS];            // w = T(k*beta), ROW-major (scan)
__device__ float g_kT [NCHK*4096];        // per chunk: k^T [d][32] (scan)
__device__ float g_att[NCHK*1024];        // attn_local (epilogue)
__device__ float g_S  [(size_t)NCHK*16384]; // per chunk: S_i col-major [c][d]
__device__ float g_u2 [NCHK*4096];        // per chunk: u' col-major [c][r]

// ----------------------------------------------------------------------------
// Kernel 1: per-chunk preprocessing. grid = 2048, block = 128
// ----------------------------------------------------------------------------
__global__ __launch_bounds__(128) void prep_kernel(
    const float* __restrict__ q, const float* __restrict__ k,
    const float* __restrict__ v, const float* __restrict__ beta)
{
    extern __shared__ float sm1[];
    float* sqT   = sm1;                // [128][33]
    float* skT   = sqT + 4224;         // [128][33]
    float* svb   = skT + 4224;         // [32][128]
    float* sA    = svb + 4096;         // [32][33]
    float* sbeta = sA  + 1056;         // [32]

    const int tid  = threadIdx.x;
    const int lane = tid & 31;
    const int warp = tid >> 5;
    const int bh = blockIdx.x >> 7;
    const int ci = blockIdx.x & 127;
    const int chk = blockIdx.x;
    const size_t base = ((size_t)bh*Ll + (size_t)ci*Cc)*Dd;

    for (int r = warp*8; r < warp*8 + 8; ++r) {
        float bet = beta[(size_t)bh*Ll + ci*Cc + r];
        const float4 xq = *(const float4*)(q + base + r*Dd + lane*4);
        const float4 xk = *(const float4*)(k + base + r*Dd + lane*4);
        const float4 xv = *(const float4*)(v + base + r*Dd + lane*4);
        float s2q = xq.x*xq.x + xq.y*xq.y + xq.z*xq.z + xq.w*xq.w;
        float s2k = xk.x*xk.x + xk.y*xk.y + xk.z*xk.z + xk.w*xk.w;
        #pragma unroll
        for (int o = 16; o; o >>= 1) {
            s2q += __shfl_xor_sync(0xffffffffu, s2q, o);
            s2k += __shfl_xor_sync(0xffffffffu, s2k, o);
        }
        float iq = rsqrtf(s2q + 1e-6f);
        float ik = rsqrtf(s2k + 1e-6f);
        float4 nq = make_float4(xq.x*iq, xq.y*iq, xq.z*iq, xq.w*iq);
        float4 nk = make_float4(xk.x*ik, xk.y*ik, xk.z*ik, xk.w*ik);
        *(float4*)(g_qn + base + r*Dd + lane*4) = nq;
        const int d0 = lane*4;
        sqT[(d0+0)*33 + r] = nq.x; sqT[(d0+1)*33 + r] = nq.y;
        sqT[(d0+2)*33 + r] = nq.z; sqT[(d0+3)*33 + r] = nq.w;
        skT[(d0+0)*33 + r] = nk.x; skT[(d0+1)*33 + r] = nk.y;
        skT[(d0+2)*33 + r] = nk.z; skT[(d0+3)*33 + r] = nk.w;
        *(float4*)(svb + r*Dd + d0) = make_float4(xv.x*bet, xv.y*bet, xv.z*bet, xv.w*bet);
        if (lane == 0) sbeta[r] = bet;
    }
    __syncthreads();

    // write k^T [d][32] for scan
    {
        const int d = tid;
        #pragma unroll
        for (int r4 = 0; r4 < 32; r4 += 4) {
            *(float4*)&g_kT[(size_t)chk*4096 + d*32 + r4] = make_float4(
                skT[d*33+r4], skT[d*33+r4+1], skT[d*33+r4+2], skT[d*33+r4+3]);
        }
    }

    // A = -beta_i (k_i.k_j) strict-lower ; E = q_i.k_j incl-lower -> g_att
    {
        const int i0 = (tid >> 3) * 2;
        const int j0 = (tid & 7) * 4;
        float a00=0,a01=0,a02=0,a03=0,a10=0,a11=0,a12=0,a13=0;
        float e00=0,e01=0,e02=0,e03=0,e10=0,e11=0,e12=0,e13=0;
        #pragma unroll 4
        for (int d = 0; d < Dd; ++d) {
            const float* kc = skT + d*33;
            const float* qc = sqT + d*33;
            float b0=kc[j0], b1=kc[j0+1], b2=kc[j0+2], b3=kc[j0+3];
            float ka0=kc[i0], ka1=kc[i0+1], qa0=qc[i0], qa1=qc[i0+1];
            a00+=ka0*b0; a01+=ka0*b1; a02+=ka0*b2; a03+=ka0*b3;
            a10+=ka1*b0; a11+=ka1*b1; a12+=ka1*b2; a13+=ka1*b3;
            e00+=qa0*b0; e01+=qa0*b1; e02+=qa0*b2; e03+=qa0*b3;
            e10+=qa1*b0; e11+=qa1*b1; e12+=qa1*b2; e13+=qa1*b3;
        }
        float nb0 = -sbeta[i0], nb1 = -sbeta[i0+1];
        sA[(i0  )*33+j0  ] = (j0  <i0  ) ? nb0*a00 : 0.f;
        sA[(i0  )*33+j0+1] = (j0+1<i0  ) ? nb0*a01 : 0.f;
        sA[(i0  )*33+j0+2] = (j0+2<i0  ) ? nb0*a02 : 0.f;
        sA[(i0  )*33+j0+3] = (j0+3<i0  ) ? nb0*a03 : 0.f;
        sA[(i0+1)*33+j0  ] = (j0  <i0+1) ? nb1*a10 : 0.f;
        sA[(i0+1)*33+j0+1] = (j0+1<i0+1) ? nb1*a11 : 0.f;
        sA[(i0+1)*33+j0+2] = (j0+2<i0+1) ? nb1*a12 : 0.f;
        sA[(i0+1)*33+j0+3] = (j0+3<i0+1) ? nb1*a13 : 0.f;
        float* ga = g_att + (size_t)chk*1024;
        ga[(i0  )*Cc+j0  ] = (j0  <=i0  ) ? e00 : 0.f;
        ga[(i0  )*Cc+j0+1] = (j0+1<=i0  ) ? e01 : 0.f;
        ga[(i0  )*Cc+j0+2] = (j0+2<=i0  ) ? e02 : 0.f;
        ga[(i0  )*Cc+j0+3] = (j0+3<=i0  ) ? e03 : 0.f;
        ga[(i0+1)*Cc+j0  ] = (j0  <=i0+1) ? e10 : 0.f;
        ga[(i0+1)*Cc+j0+1] = (j0+1<=i0+1) ? e11 : 0.f;
        ga[(i0+1)*Cc+j0+2] = (j0+2<=i0+1) ? e12 : 0.f;
        ga[(i0+1)*Cc+j0+3] = (j0+3<=i0+1) ? e13 : 0.f;
    }
    __syncthreads();

    // forward substitution (warp 0), then += I
    if (warp == 0) {
        for (int i = 1; i < 32; ++i) {
            float rv  = sA[i*33 + lane];
            float acc = rv;
            for (int j = 0; j < i; ++j)
                acc += __shfl_sync(0xffffffffu, rv, j) * sA[j*33 + lane];
            sA[i*33 + lane] = acc;
            __syncwarp();
        }
        sA[lane*33 + lane] += 1.0f;
    }
    __syncthreads();

    // u = T(v*beta) row-major ; w = T(k*beta) row-major (coalesced scalar STG)
    {
        const int d = tid;
        #pragma unroll
        for (int rb = 0; rb < 4; ++rb) {
            const int r0 = rb*8;
            float ar[8];
            #pragma unroll
            for (int rr = 0; rr < 8; ++rr) ar[rr] = sA[(r0+rr)*33 + lane];
            float au[8] = {0,0,0,0,0,0,0,0};
            float aw[8] = {0,0,0,0,0,0,0,0};
            for (int j = 0; j < 32; ++j) {
                float vb = svb[j*Dd + d];
                float kb = skT[d*33 + j] * sbeta[j];
                #pragma unroll
                for (int rr = 0; rr < 8; ++rr) {
                    float a = __shfl_sync(0xffffffffu, ar[rr], j);
                    au[rr] += a*vb;
                    aw[rr] += a*kb;
                }
            }
            #pragma unroll
            for (int rr = 0; rr < 8; ++rr) {
                g_u[base + (size_t)(r0+rr)*Dd + d] = au[rr];
                g_w[base + (size_t)(r0+rr)*Dd + d] = aw[rr];
            }
        }
    }
}

// ----------------------------------------------------------------------------
// Kernel 2: sequential scan (state only). grid = (8,16), block = 512.
// ----------------------------------------------------------------------------
#define SWD 132            // w row-major row stride
#define SKD 36             // k^T row stride
#define SST 20             // S / Yp / u2 row stride
#define SW_SZ (32*SWD)     // 4224
#define SK_SZ (128*SKD)    // 4608

__global__ __launch_bounds__(512, 1) void scan_kernel(float* __restrict__ out)
{
    extern __shared__ float sm2[];
    float* sw  = sm2;                   // [2][32][132]  w row-major
    float* sk  = sw  + 2*SW_SZ;         // [2][128][36]  k^T
    float* sS  = sk  + 2*SK_SZ;         // [128][20]
    float* sYp = sS  + 2560;            // [8][32][20]
    float* su2 = sYp + 5120;            // [32][20]

    const int cb = blockIdx.x;
    const int bh = blockIdx.y;
    const int colbase = cb * DVB;
    const int tid  = threadIdx.x;
    const int lane = tid & 31;
    const int warp = tid >> 5;

    // Y roles: dq = d-16-chunk (0..7), cw = col-half (0..1); lane = r
    const int dq = warp >> 1;
    const int cw8 = (warp & 1) * 8;
    // update roles: ud (0..3) x uc (0..3); lane owns S[ud*32+lane][uc*4..+3]
    const int sd  = (warp >> 2)*32 + lane;
    const int uc4 = (warp & 3) * 4;
    // u' roles (tid<128)
    const int tw4 = (tid >> 5) * 4;
    // prefetch roles
    const int wm  = tid >> 4;            // w row 0..31
    const int wd0 = (tid & 15) * 8;      // w col
    const int kd  = tid >> 2;            // k d-row 0..127
    const int kr0 = (tid & 3) * 8;       // k r

    u64t s01 = 0ull, s23 = 0ull;         // packed S tile (2 cols each)
    for (int i = tid; i < 2560; i += 512) sS[i] = 0.f;

    float4 rw0, rw1, rk0, rk1, ru;

    // prefetch + commit chunk 0
    {
        const size_t pb = ((size_t)bh*Ll)*Dd;
        rw0 = *(const float4*)(g_w + pb + wm*Dd + wd0);
        rw1 = *(const float4*)(g_w + pb + wm*Dd + wd0 + 4);
        rk0 = *(const float4*)(g_kT + (size_t)(bh*NCH)*4096 + kd*32 + kr0);
        rk1 = *(const float4*)(g_kT + (size_t)(bh*NCH)*4096 + kd*32 + kr0 + 4);
        if (tid < 128)
            ru = *(const float4*)(g_u + pb + (size_t)(tid&31)*Dd + colbase + tw4);
        *(float4*)&sw[wm*SWD + wd0    ] = rw0;
        *(float4*)&sw[wm*SWD + wd0 + 4] = rw1;
        *(float4*)&sk[kd*SKD + kr0    ] = rk0;
        *(float4*)&sk[kd*SKD + kr0 + 4] = rk1;
    }
    __syncthreads();

    for (int ci = 0; ci < NCH; ++ci) {
        const int buf = ci & 1;
        const int chk = bh*NCH + ci;

        // persist S_i (pre-chunk), col-major [c][d]
        {
            float2 a = up2(s01), b = up2(s23);
            float* gs = g_S + (size_t)chk*16384 + (size_t)(colbase + uc4)*128 + sd;
            gs[0] = a.x; gs[128] = a.y; gs[256] = b.x; gs[384] = b.y;
        }
        // prefetch chunk ci+1
        float4 ru_next = ru;
        if (ci + 1 < NCH) {
            const size_t pb = ((size_t)bh*Ll + (size_t)(ci+1)*Cc)*Dd;
            rw0 = *(const float4*)(g_w + pb + wm*Dd + wd0);
            rw1 = *(const float4*)(g_w + pb + wm*Dd + wd0 + 4);
            rk0 = *(const float4*)(g_kT + (size_t)(chk+1)*4096 + kd*32 + kr0);
            rk1 = *(const float4*)(g_kT + (size_t)(chk+1)*4096 + kd*32 + kr0 + 4);
            if (tid < 128)
                ru_next = *(const float4*)(g_u + pb + (size_t)(tid&31)*Dd + colbase + tw4);
        }

        // Y: partial of w(32x128) @ S(128x16); warp: d in [dq*16, +16), 8 cols
        {
            const float* bw = sw + buf*SW_SZ + lane*SWD;
            u64t y0=0ull, y1=0ull, y2=0ull, y3=0ull;
            #pragma unroll
            for (int j4 = 0; j4 < 4; ++j4) {
                const int d = dq*16 + j4*4;
                float4 wv = *(const float4*)(bw + d);
                #pragma unroll
                for (int i = 0; i < 4; ++i) {
                    float xs = (i==0)?wv.x:(i==1)?wv.y:(i==2)?wv.z:wv.w;
                    u64t xx = pk2s(xs);
                    ulonglong2 sa = *(const ulonglong2*)&sS[(d+i)*SST + cw8];
                    ulonglong2 sb = *(const ulonglong2*)&sS[(d+i)*SST + cw8 + 4];
                    y0 = f2(xx, sa.x, y0); y1 = f2(xx, sa.y, y1);
                    y2 = f2(xx, sb.x, y2); y3 = f2(xx, sb.y, y3);
                }
            }
            ulonglong2 o1; o1.x = y0; o1.y = y1;
            ulonglong2 o2; o2.x = y2; o2.y = y3;
            *(ulonglong2*)&sYp[dq*640 + lane*SST + cw8    ] = o1;
            *(ulonglong2*)&sYp[dq*640 + lane*SST + cw8 + 4] = o2;
        }
        __syncthreads();

        // u' = u - w@S  (tid<128)
        if (tid < 128) {
            const int r = lane;
            float4 acc = ru;
            #pragma unroll
            for (int d8 = 0; d8 < 8; ++d8) {
                float4 p = *(const float4*)&sYp[d8*640 + r*SST + tw4];
                acc.x -= p.x; acc.y -= p.y; acc.z -= p.z; acc.w -= p.w;
            }
            *(float4*)&su2[r*SST + tw4] = acc;
            float* gu = g_u2 + (size_t)chk*4096 + (colbase + tw4)*32 + r;
            gu[0] = acc.x; gu[32] = acc.y; gu[64] = acc.z; gu[96] = acc.w;
        }
        // commit next chunk into other buffer (overlaps u')
        if (ci + 1 < NCH) {
            const int b2 = (ci+1) & 1;
            float* dw = sw + b2*SW_SZ;
            float* dk = sk + b2*SK_SZ;
            *(float4*)&dw[wm*SWD + wd0    ] = rw0;
            *(float4*)&dw[wm*SWD + wd0 + 4] = rw1;
            *(float4*)&dk[kd*SKD + kr0    ] = rk0;
            *(float4*)&dk[kd*SKD + kr0 + 4] = rk1;
            ru = ru_next;
        }
        __syncthreads();

        // S += k^T @ u'  (all 16 warps, packed accumulators)
        {
            const float* kp = sk + buf*SK_SZ + sd*SKD;
            #pragma unroll
            for (int r4 = 0; r4 < 8; ++r4) {
                float4 k4 = *(const float4*)(kp + r4*4);
                #pragma unroll
                for (int i = 0; i < 4; ++i) {
                    float ks = (i==0)?k4.x:(i==1)?k4.y:(i==2)?k4.z:k4.w;
                    u64t kk = pk2s(ks);
                    ulonglong2 uu = *(const ulonglong2*)&su2[(r4*4+i)*SST + uc4];
                    s01 = f2(kk, uu.x, s01);
                    s23 = f2(kk, uu.y, s23);
                }
            }
            ulonglong2 sv; sv.x = s01; sv.y = s23;
            *(ulonglong2*)&sS[sd*SST + uc4] = sv;
        }
        __syncthreads();
    }

    // final S -> out
    {
        float2 a = up2(s01), b = up2(s23);
        *(float4*)&out[O_ELEMS + ((size_t)bh*Dd + sd)*Dd + colbase + uc4] =
            make_float4(a.x, a.y, b.x, b.y);
    }
}

// ----------------------------------------------------------------------------
// Kernel 3: epilogue o = q@S_i + A@u'_i. grid = (NCH, BHh), block = 256.
// ----------------------------------------------------------------------------
#define AST 36

__global__ __launch_bounds__(256) void epi_kernel(float* __restrict__ out)
{
    extern __shared__ float sm3[];
    float* sS = sm3;              // [128][132] row-major S
    float* sq = sS + 128*132;     // [32][132]
    float* su = sq + 32*132;      // [32][132]
    float* sA = su + 32*132;      // [32][36]

    const int ci = blockIdx.x;
    const int bh = blockIdx.y;
    const int chk = bh*NCH + ci;
    const int tid = threadIdx.x;
    const size_t qbase = ((size_t)bh*Ll + (size_t)ci*Cc)*Dd;

    {
        const int c = tid >> 1;
        const int db = (tid & 1) * 64;
        const float* gs = g_S + (size_t)chk*16384 + (size_t)c*128 + db;
        #pragma unroll
        for (int i = 0; i < 16; ++i) {
            float4 f = *(const float4*)(gs + i*4);
            int d = db + i*4;
            sS[(d  )*132 + c] = f.x; sS[(d+1)*132 + c] = f.y;
            sS[(d+2)*132 + c] = f.z; sS[(d+3)*132 + c] = f.w;
        }
    }
    {
        #pragma unroll
        for (int t = 0; t < 4; ++t) {
            int i4 = (tid + t*256) * 4;
            float4 f = *(const float4*)(g_qn + qbase + i4);
            *(float4*)&sq[(i4 >> 7)*132 + (i4 & 127)] = f;
        }
    }
    {
        #pragma unroll
        for (int t = 0; t < 4; ++t) {
            int i4 = (tid + t*256) * 4;
            float4 f = *(const float4*)(g_u2 + (size_t)chk*4096 + i4);
            int c = i4 >> 5, r = i4 & 31;
            su[(r  )*132 + c] = f.x; su[(r+1)*132 + c] = f.y;
            su[(r+2)*132 + c] = f.z; su[(r+3)*132 + c] = f.w;
        }
    }
    {
        int i4 = tid * 4;
        float4 f = *(const float4*)(g_att + (size_t)chk*1024 + i4);
        *(float4*)&sA[(i4 >> 5)*AST + (i4 & 31)] = f;
    }
    __syncthreads();

    const int m0 = (tid >> 4) * 2;
    const int m1 = m0 + 1;
    const int cbk = (tid & 15) * 8;
    float4 a00 = make_float4(0,0,0,0), a01 = a00, a10 = a00, a11 = a00;
    #pragma unroll 8
    for (int d = 0; d < 128; ++d) {
        float q0 = sq[m0*132 + d];
        float q1 = sq[m1*132 + d];
        float4 s0 = *(const float4*)&sS[d*132 + cbk];
        float4 s1 = *(const float4*)&sS[d*132 + cbk + 4];
        a00.x += q0*s0.x; a00.y += q0*s0.y; a00.z += q0*s0.z; a00.w += q0*s0.w;
        a01.x += q0*s1.x; a01.y += q0*s1.y; a01.z += q0*s1.z; a01.w += q0*s1.w;
        a10.x += q1*s0.x; a10.y += q1*s0.y; a10.z += q1*s0.z; a10.w += q1*s0.w;
        a11.x += q1*s1.x; a11.y += q1*s1.y; a11.z += q1*s1.z; a11.w += q1*s1.w;
    }
    #pragma unroll 8
    for (int j = 0; j < 32; ++j) {
        float p0 = sA[m0*AST + j];
        float p1 = sA[m1*AST + j];
        float4 u0 = *(const float4*)&su[j*132 + cbk];
        float4 u1 = *(const float4*)&su[j*132 + cbk + 4];
        a00.x += p0*u0.x; a00.y += p0*u0.y; a00.z += p0*u0.z; a00.w += p0*u0.w;
        a01.x += p0*u1.x; a01.y += p0*u1.y; a01.z += p0*u1.z; a01.w += p0*u1.w;
        a10.x += p1*u0.x; a10.y += p1*u0.y; a10.z += p1*u0.z; a10.w += p1*u0.w;
        a11.x += p1*u1.x; a11.y += p1*u1.y; a11.z += p1*u1.z; a11.w += p1*u1.w;
    }
    float* o0 = out + qbase + (size_t)m0*Dd + cbk;
    float* o1 = out + qbase + (size_t)m1*Dd + cbk;
    *(float4*)(o0)     = a00; *(float4*)(o0 + 4) = a01;
    *(float4*)(o1)     = a10; *(float4*)(o1 + 4) = a11;
}

// ----------------------------------------------------------------------------
extern "C" void kernel_launch(void* const* d_in, const int* in_sizes, int n_in,
                              void* d_out, int out_size)
{
    const float* q    = (const float*)d_in[0];
    const float* k    = (const float*)d_in[1];
    const float* v    = (const float*)d_in[2];
    const float* beta = (const float*)d_in[3];
    float* out = (float*)d_out;

    const int smem1 = (2*4224 + 4096 + 1056 + 32) * 4;                 // 54528
    const int smem2 = (2*SW_SZ + 2*SK_SZ + 2560 + 5120 + 640) * 4;     // 103936
    const int smem3 = (128*132 + 32*132 + 32*132 + 32*AST) * 4;        // 105984
    cudaFuncSetAttribute(prep_kernel, cudaFuncAttributeMaxDynamicSharedMemorySize, smem1);
    cudaFuncSetAttribute(scan_kernel, cudaFuncAttributeMaxDynamicSharedMemorySize, smem2);
    cudaFuncSetAttribute(epi_kernel,  cudaFuncAttributeMaxDynamicSharedMemorySize, smem3);

    prep_kernel<<<NCHK, 128, smem1>>>(q, k, v, beta);
    scan_kernel<<<dim3(NDVB, BHh), 512, smem2>>>(out);
    epi_kernel<<<dim3(NCH, BHh), 256, smem3>>>(out);
}